// round 1
// baseline (speedup 1.0000x reference)
#include <cuda_runtime.h>

#define BSZ  256
#define NTOK 196
#define DIM  384
#define NH   8
#define KD   32
#define VD   128
#define HPER 192      // 2*KD + VD
#define HID  1536     // HPER*NH
#define NPAIR 38416   // 196*196
#define MROWS (BSZ*NTOK)   // 50176

// ---------------- scratch (static device globals; no allocs allowed) ----------
__device__ float g_qkv[(size_t)MROWS * HID];          // [B*N, 1536]
__device__ float g_attn_out[(size_t)MROWS * NH * VD]; // [B*N, 1024]
__device__ float g_bias[(size_t)NH * NPAIR];          // [8, 196, 196]

// ---------------- bias table precompute --------------------------------------
// bias_idxs may arrive as int32 (jax default, x64 disabled) or int64.
// Sniff: word[1] of the raw buffer is 0 iff the data is int64 (high word of
// idx 0); genuine int32 data has word[1] == 1 (first new offset index).
__global__ void bias_fill_kernel(const int* __restrict__ idx_raw,
                                 const float* __restrict__ ab, int n_off) {
    int i = blockIdx.x * blockDim.x + threadIdx.x;
    if (i >= NPAIR) return;
    bool is64 = (idx_raw[1] == 0);
    int idx = is64 ? idx_raw[2 * i] : idx_raw[i];
#pragma unroll
    for (int h = 0; h < NH; h++)
        g_bias[(size_t)h * NPAIR + i] = ab[h * n_off + idx];
}

// ---------------- SGEMM: C[M,N] = A[M,K] @ W[N,K]^T + bias[N] -----------------
// Both A and W are K-contiguous (NT gemm). 128x128 tile, BK=16, 8x8 per thread.
// All dims here are exact multiples (M=50176=392*128, N in {1536,384}, K in {384,1024}).
__global__ __launch_bounds__(256) void gemm_nt_kernel(
    const float* __restrict__ A, const float* __restrict__ W,
    const float* __restrict__ bias, float* __restrict__ C,
    int M, int N, int K)
{
    __shared__ float As[16][128];
    __shared__ float Ws[16][128];

    const int tid = threadIdx.x;
    const int tx = tid & 15;        // 0..15  -> N micro
    const int ty = tid >> 4;        // 0..15  -> M micro
    const int bm = blockIdx.y, bn = blockIdx.x;

    const float* Ab = A + (size_t)bm * 128 * K;
    const float* Wb = W + (size_t)bn * 128 * K;

    float acc[8][8];
#pragma unroll
    for (int i = 0; i < 8; i++)
#pragma unroll
        for (int j = 0; j < 8; j++) acc[i][j] = 0.0f;

    for (int kt = 0; kt < K; kt += 16) {
        // cooperative load: 128x16 tiles, transposed into smem [k][row]
#pragma unroll
        for (int l = 0; l < 2; l++) {
            int i   = tid + l * 256;       // 0..511
            int row = i >> 2;              // 0..127
            int c4  = (i & 3) * 4;         // 0,4,8,12
            float4 av = *(const float4*)(Ab + (size_t)row * K + kt + c4);
            As[c4 + 0][row] = av.x; As[c4 + 1][row] = av.y;
            As[c4 + 2][row] = av.z; As[c4 + 3][row] = av.w;
            float4 wv = *(const float4*)(Wb + (size_t)row * K + kt + c4);
            Ws[c4 + 0][row] = wv.x; Ws[c4 + 1][row] = wv.y;
            Ws[c4 + 2][row] = wv.z; Ws[c4 + 3][row] = wv.w;
        }
        __syncthreads();

#pragma unroll
        for (int kk = 0; kk < 16; kk++) {
            float a[8], b[8];
#pragma unroll
            for (int i = 0; i < 8; i++) a[i] = As[kk][ty * 8 + i];
#pragma unroll
            for (int j = 0; j < 8; j++) b[j] = Ws[kk][tx * 8 + j];
#pragma unroll
            for (int i = 0; i < 8; i++)
#pragma unroll
                for (int j = 0; j < 8; j++) acc[i][j] = fmaf(a[i], b[j], acc[i][j]);
        }
        __syncthreads();
    }

    // epilogue with bias
#pragma unroll
    for (int i = 0; i < 8; i++) {
        size_t crow = (size_t)(bm * 128 + ty * 8 + i) * N + bn * 128 + tx * 8;
#pragma unroll
        for (int j = 0; j < 8; j++)
            C[crow + j] = acc[i][j] + bias[bn * 128 + tx * 8 + j];
    }
}

// ---------------- fused attention: one CTA per (b,h) --------------------------
// K tile (196x32) and V tile (196x128) live in smem (125,440 B dynamic).
// One thread per query row n; two-pass (max, then exp/accumulate) branch-free
// online softmax; o[128] accumulator in registers.
__global__ __launch_bounds__(224, 1) void attn_kernel() {
    extern __shared__ float sh[];
    float* k_s = sh;                 // [196][32]
    float* v_s = sh + NTOK * KD;     // [196][128]

    const int b = blockIdx.y, h = blockIdx.x;
    const int tid = threadIdx.x;
    const float* qkv_b = g_qkv + (size_t)b * NTOK * HID + h * HPER;

    for (int i = tid; i < NTOK * KD; i += 224) {
        int m = i / KD, c = i - m * KD;
        k_s[i] = qkv_b[(size_t)m * HID + KD + c];
    }
    for (int i = tid; i < NTOK * VD; i += 224) {
        int m = i / VD, c = i - m * VD;
        v_s[i] = qkv_b[(size_t)m * HID + 2 * KD + c];
    }
    __syncthreads();

    if (tid >= NTOK) return;   // no further syncs
    const int n = tid;

    float q[KD];
#pragma unroll
    for (int c = 0; c < KD; c++) q[c] = qkv_b[(size_t)n * HID + c];

    const float* brow = g_bias + (size_t)h * NPAIR + n * NTOK;
    const float scale = 0.1767766952966369f;  // 32^-0.5

    // pass 1: row max
    float mx = -1e30f;
    for (int m = 0; m < NTOK; m++) {
        float s = 0.0f;
#pragma unroll
        for (int c = 0; c < KD; c++) s = fmaf(q[c], k_s[m * KD + c], s);
        s = fmaf(s, scale, __ldg(brow + m));
        mx = fmaxf(mx, s);
    }

    // pass 2: exp + PV accumulate
    float l = 0.0f;
    float o[VD];
#pragma unroll
    for (int d = 0; d < VD; d++) o[d] = 0.0f;

    for (int m = 0; m < NTOK; m++) {
        float s = 0.0f;
#pragma unroll
        for (int c = 0; c < KD; c++) s = fmaf(q[c], k_s[m * KD + c], s);
        s = fmaf(s, scale, __ldg(brow + m));
        float p = __expf(s - mx);
        l += p;
        const float* vrow = v_s + m * VD;
#pragma unroll
        for (int d = 0; d < VD; d++) o[d] = fmaf(p, vrow[d], o[d]);
    }

    float inv = 1.0f / l;
    float* outp = g_attn_out + ((size_t)(b * NTOK + n) * NH + h) * VD;
#pragma unroll
    for (int d = 0; d < VD; d++) outp[d] = o[d] * inv;
}

// ---------------- launch ------------------------------------------------------
extern "C" void kernel_launch(void* const* d_in, const int* in_sizes, int n_in,
                              void* d_out, int out_size) {
    const float* x     = (const float*)d_in[0];
    const float* Wqkv  = (const float*)d_in[1];
    const float* bqkv  = (const float*)d_in[2];
    const float* Wproj = (const float*)d_in[3];
    const float* bproj = (const float*)d_in[4];
    const float* ab    = (const float*)d_in[5];
    const int*   idxs  = (const int*)  d_in[6];
    float* out = (float*)d_out;

    int n_off = in_sizes[5] / NH;   // 196

    void *p_qkv, *p_ao;
    cudaGetSymbolAddress(&p_qkv, g_qkv);
    cudaGetSymbolAddress(&p_ao,  g_attn_out);

    const int attn_smem = (NTOK * KD + NTOK * VD) * (int)sizeof(float); // 125440
    cudaFuncSetAttribute(attn_kernel,
                         cudaFuncAttributeMaxDynamicSharedMemorySize, attn_smem);

    // 1) bias table
    bias_fill_kernel<<<(NPAIR + 255) / 256, 256>>>(idxs, ab, n_off);

    // 2) QKV gemm: [50176,384] x [1536,384]^T -> g_qkv
    gemm_nt_kernel<<<dim3(HID / 128, MROWS / 128), 256>>>(
        x, Wqkv, bqkv, (float*)p_qkv, MROWS, HID, DIM);

    // 3) fused attention -> g_attn_out
    attn_kernel<<<dim3(NH, BSZ), 224, attn_smem>>>();

    // 4) proj gemm: [50176,1024] x [384,1024]^T -> out
    gemm_nt_kernel<<<dim3(DIM / 128, MROWS / 128), 256>>>(
        (const float*)p_ao, Wproj, bproj, out, MROWS, DIM, NH * VD);
}